// round 6
// baseline (speedup 1.0000x reference)
#include <cuda_runtime.h>
#include <cuda_bf16.h>
#include <math.h>
#include <stdint.h>

// ---------------- problem constants ----------------
#define Bn    32
#define Hs    56
#define Ws_   56
#define Cc    192
#define WS    7
#define SS    3
#define NH    6
#define Nn    49
#define HD    32
#define BW    2048
#define ROWS  100352
#define HID   768
#define SCALE 0.17677669529663687f
#define LNEPS 1e-5f

// ---------------- helpers ----------------
__device__ __forceinline__ uint32_t smem_u32(const void* p) {
    uint32_t a;
    asm("{ .reg .u64 t; cvta.to.shared.u64 t, %1; cvt.u32.u64 %0, t; }" : "=r"(a) : "l"(p));
    return a;
}

#define LDSM4(r, a) \
    asm volatile("ldmatrix.sync.aligned.m8n8.x4.shared.b16 {%0,%1,%2,%3}, [%4];" \
        : "=r"((r)[0]), "=r"((r)[1]), "=r"((r)[2]), "=r"((r)[3]) : "r"(a))

#define MMA16816(d, a, b0, b1) \
    asm volatile("mma.sync.aligned.m16n8k16.row.col.f32.bf16.bf16.f32 " \
        "{%0,%1,%2,%3}, {%4,%5,%6,%7}, {%8,%9}, {%0,%1,%2,%3};" \
        : "+f"((d)[0]), "+f"((d)[1]), "+f"((d)[2]), "+f"((d)[3]) \
        : "r"((a)[0]), "r"((a)[1]), "r"((a)[2]), "r"((a)[3]), "r"(b0), "r"(b1))

__device__ __forceinline__ void split2(float v, __nv_bfloat16& h, __nv_bfloat16& l) {
    h = __float2bfloat16(v);
    l = __float2bfloat16(v - __bfloat162float(h));
}

// ---------------- scratch ----------------
__device__ __nv_bfloat16 g_xw_h[(size_t)ROWS * Cc];
__device__ __nv_bfloat16 g_xw_l[(size_t)ROWS * Cc];
__device__ float         g_qkv[(size_t)ROWS * 3 * Cc];
__device__ __nv_bfloat16 g_ao_h[(size_t)ROWS * Cc];
__device__ __nv_bfloat16 g_ao_l[(size_t)ROWS * Cc];
__device__ float         g_h[(size_t)ROWS * Cc];
__device__ __nv_bfloat16 g_hid_h[(size_t)ROWS * HID];
__device__ __nv_bfloat16 g_hid_l[(size_t)ROWS * HID];
__device__ __nv_bfloat16 g_wq_h[3 * Cc * Cc], g_wq_l[3 * Cc * Cc];
__device__ __nv_bfloat16 g_wp_h[Cc * Cc],     g_wp_l[Cc * Cc];
__device__ __nv_bfloat16 g_f1_h[HID * Cc],    g_f1_l[HID * Cc];
__device__ __nv_bfloat16 g_f2_h[Cc * HID],    g_f2_l[Cc * HID];

// ---------------- weight split ----------------
__global__ void convert_kernel(const float* __restrict__ w,
                               __nv_bfloat16* __restrict__ hi,
                               __nv_bfloat16* __restrict__ lo, int n) {
    int i = blockIdx.x * 256 + threadIdx.x;
    if (i < n) split2(w[i], hi[i], lo[i]);
}

// ---------------- LN kernels (write bf16 hi/lo) ----------------
__global__ void ln1_gather_kernel(const float* __restrict__ x,
                                  const float* __restrict__ g, const float* __restrict__ b,
                                  __nv_bfloat16* __restrict__ oh, __nv_bfloat16* __restrict__ ol) {
    int r = blockIdx.x * 8 + (threadIdx.x >> 5);
    if (r >= ROWS) return;
    int lane = threadIdx.x & 31;
    int b_ = r / Nn, t = r - b_ * Nn;
    int bb = b_ >> 6, w = b_ & 63;
    int hr = (w >> 3) * WS + t / WS;
    int wr = (w & 7) * WS + t % WS;
    int sh = hr + SS; if (sh >= Hs) sh -= Hs;
    int sw = wr + SS; if (sw >= Ws_) sw -= Ws_;
    const float* src = x + ((size_t)(bb * Hs * Ws_ + sh * Ws_ + sw)) * Cc;
    float v[6], s = 0.f, s2 = 0.f;
    #pragma unroll
    for (int j = 0; j < 6; j++) { v[j] = src[lane + 32 * j]; s += v[j]; s2 += v[j] * v[j]; }
    #pragma unroll
    for (int o = 16; o; o >>= 1) { s += __shfl_xor_sync(~0u, s, o); s2 += __shfl_xor_sync(~0u, s2, o); }
    float mu = s * (1.f / Cc), var = s2 * (1.f / Cc) - mu * mu;
    float rs = rsqrtf(var + LNEPS);
    size_t d0 = (size_t)r * Cc;
    #pragma unroll
    for (int j = 0; j < 6; j++) {
        int c = lane + 32 * j;
        float y = (v[j] - mu) * rs * g[c] + b[c];
        split2(y, oh[d0 + c], ol[d0 + c]);
    }
}

__global__ void ln_plain_kernel(const float* __restrict__ x,
                                const float* __restrict__ g, const float* __restrict__ b,
                                __nv_bfloat16* __restrict__ oh, __nv_bfloat16* __restrict__ ol) {
    int r = blockIdx.x * 8 + (threadIdx.x >> 5);
    if (r >= ROWS) return;
    int lane = threadIdx.x & 31;
    const float* src = x + (size_t)r * Cc;
    float v[6], s = 0.f, s2 = 0.f;
    #pragma unroll
    for (int j = 0; j < 6; j++) { v[j] = src[lane + 32 * j]; s += v[j]; s2 += v[j] * v[j]; }
    #pragma unroll
    for (int o = 16; o; o >>= 1) { s += __shfl_xor_sync(~0u, s, o); s2 += __shfl_xor_sync(~0u, s2, o); }
    float mu = s * (1.f / Cc), var = s2 * (1.f / Cc) - mu * mu;
    float rs = rsqrtf(var + LNEPS);
    size_t d0 = (size_t)r * Cc;
    #pragma unroll
    for (int j = 0; j < 6; j++) {
        int c = lane + 32 * j;
        float y = (v[j] - mu) * rs * g[c] + b[c];
        split2(y, oh[d0 + c], ol[d0 + c]);
    }
}

// ---------------- mma.sync bf16 GEMM, 3-term split, BM=256 BN=64 ----------
// 8 warps, each owns a 32(m) x 64(n) warp tile (wm = wid).
#define BKt   32
#define ASTR  40                             // 32 + 8 pad (bf16 elems)
#define OFF_AH 0
#define OFF_AL 20480
#define OFF_BH 40960
#define OFF_BL 46080
#define BUF_SZ 51200
#define SMEM_TOT (BUF_SZ * 2)                // 102400

template <int N_, int K_, int EPI>
__global__ __launch_bounds__(256) void gemm_mma(
    const __nv_bfloat16* __restrict__ Ah, const __nv_bfloat16* __restrict__ Al,
    const __nv_bfloat16* __restrict__ Wh, const __nv_bfloat16* __restrict__ Wl,
    const float* __restrict__ bias, float* __restrict__ Co,
    const float* __restrict__ resid,
    __nv_bfloat16* __restrict__ Oh, __nv_bfloat16* __restrict__ Ol) {
    extern __shared__ char smem[];
    const int t = threadIdx.x, lane = t & 31, wid = t >> 5;
    const int wm = wid;                       // warp m-stripe 0..7
    const int m0 = blockIdx.y * 256, n0 = blockIdx.x * 64;
    constexpr int NKT = K_ / BKt;

    float acc[2][8][4];
    #pragma unroll
    for (int i = 0; i < 2; i++)
        #pragma unroll
        for (int j = 0; j < 8; j++)
            #pragma unroll
            for (int k = 0; k < 4; k++) acc[i][j][k] = 0.f;

    const int arow = t >> 2, akq = t & 3;     // 64 rows/pass, 4 quads of 8 cols
    // ---- prologue: tile 0 -> buffer 0 ----
    {
        #pragma unroll
        for (int l = 0; l < 4; l++) {
            int row = arow + l * 64;
            uint32_t so = (uint32_t)row * (ASTR * 2) + akq * 16;
            *(uint4*)(smem + OFF_AH + so) = *(const uint4*)(Ah + (size_t)(m0 + row) * K_ + akq * 8);
            *(uint4*)(smem + OFF_AL + so) = *(const uint4*)(Al + (size_t)(m0 + row) * K_ + akq * 8);
        }
        uint32_t so = (uint32_t)arow * (ASTR * 2) + akq * 16;
        *(uint4*)(smem + OFF_BH + so) = *(const uint4*)(Wh + (size_t)(n0 + arow) * K_ + akq * 8);
        *(uint4*)(smem + OFF_BL + so) = *(const uint4*)(Wl + (size_t)(n0 + arow) * K_ + akq * 8);
    }
    __syncthreads();

    const int fr = lane & 15;
    const int fc = (lane >> 4) * 8;

    for (int kt = 0; kt < NKT; kt++) {
        char* buf = smem + (kt & 1) * BUF_SZ;
        uint4 pah[4], pal[4], pbh, pbl;
        if (kt + 1 < NKT) {
            int k0n = (kt + 1) * BKt;
            #pragma unroll
            for (int l = 0; l < 4; l++) {
                int row = arow + l * 64;
                pah[l] = *(const uint4*)(Ah + (size_t)(m0 + row) * K_ + k0n + akq * 8);
                pal[l] = *(const uint4*)(Al + (size_t)(m0 + row) * K_ + k0n + akq * 8);
            }
            pbh = *(const uint4*)(Wh + (size_t)(n0 + arow) * K_ + k0n + akq * 8);
            pbl = *(const uint4*)(Wl + (size_t)(n0 + arow) * K_ + k0n + akq * 8);
        }

        const uint32_t sAh = smem_u32(buf + OFF_AH);
        const uint32_t sAl = smem_u32(buf + OFF_AL);
        const uint32_t sBh = smem_u32(buf + OFF_BH);
        const uint32_t sBl = smem_u32(buf + OFF_BL);

        #pragma unroll
        for (int ks = 0; ks < 2; ks++) {
            int col = ks * 16 + fc;
            uint32_t ah[2][4], al[2][4], bh[4][4], bl[4][4];
            #pragma unroll
            for (int mf = 0; mf < 2; mf++) {
                uint32_t off = (uint32_t)(wm * 32 + mf * 16 + fr) * (ASTR * 2) + col * 2;
                LDSM4(ah[mf], sAh + off);
                LDSM4(al[mf], sAl + off);
            }
            #pragma unroll
            for (int nf2 = 0; nf2 < 4; nf2++) {
                uint32_t off = (uint32_t)(nf2 * 16 + fr) * (ASTR * 2) + col * 2;
                LDSM4(bh[nf2], sBh + off);
                LDSM4(bl[nf2], sBl + off);
            }
            #pragma unroll
            for (int mf = 0; mf < 2; mf++)
                #pragma unroll
                for (int nf = 0; nf < 8; nf++) {
                    int n2 = nf >> 1, sel = nf & 1;
                    MMA16816(acc[mf][nf], ah[mf], bh[n2][sel], bh[n2][sel + 2]);
                }
            #pragma unroll
            for (int mf = 0; mf < 2; mf++)
                #pragma unroll
                for (int nf = 0; nf < 8; nf++) {
                    int n2 = nf >> 1, sel = nf & 1;
                    MMA16816(acc[mf][nf], ah[mf], bl[n2][sel], bl[n2][sel + 2]);
                }
            #pragma unroll
            for (int mf = 0; mf < 2; mf++)
                #pragma unroll
                for (int nf = 0; nf < 8; nf++) {
                    int n2 = nf >> 1, sel = nf & 1;
                    MMA16816(acc[mf][nf], al[mf], bh[n2][sel], bh[n2][sel + 2]);
                }
        }

        if (kt + 1 < NKT) {
            char* nb = smem + ((kt + 1) & 1) * BUF_SZ;
            #pragma unroll
            for (int l = 0; l < 4; l++) {
                int row = arow + l * 64;
                uint32_t so = (uint32_t)row * (ASTR * 2) + akq * 16;
                *(uint4*)(nb + OFF_AH + so) = pah[l];
                *(uint4*)(nb + OFF_AL + so) = pal[l];
            }
            uint32_t so = (uint32_t)arow * (ASTR * 2) + akq * 16;
            *(uint4*)(nb + OFF_BH + so) = pbh;
            *(uint4*)(nb + OFF_BL + so) = pbl;
            __syncthreads();
        }
    }

    // ---- epilogue ----
    const int r_in = lane >> 2, c_in = (lane & 3) * 2;
    #pragma unroll
    for (int mf = 0; mf < 2; mf++) {
        #pragma unroll
        for (int rr = 0; rr < 2; rr++) {
            int m = m0 + wm * 32 + mf * 16 + r_in + rr * 8;
            size_t dbase;
            if (EPI == 2) {
                int b_ = m / Nn, tok = m - b_ * Nn;
                int bb = b_ >> 6, w = b_ & 63;
                int hr = (w >> 3) * WS + tok / WS;
                int wr = (w & 7) * WS + tok % WS;
                int dh = hr + SS; if (dh >= Hs) dh -= Hs;
                int dw = wr + SS; if (dw >= Ws_) dw -= Ws_;
                dbase = ((size_t)(bb * Hs * Ws_ + dh * Ws_ + dw)) * Cc;
            } else {
                dbase = (size_t)m * N_;
            }
            #pragma unroll
            for (int nf = 0; nf < 8; nf++) {
                int col = n0 + nf * 8 + c_in;
                float2 bv = *(const float2*)(bias + col);
                float v0 = acc[mf][nf][rr * 2]     + bv.x;
                float v1 = acc[mf][nf][rr * 2 + 1] + bv.y;
                if (EPI == 0) {
                    *(float2*)(Co + dbase + col) = make_float2(v0, v1);
                } else if (EPI == 1) {
                    v0 = 0.5f * v0 * (1.f + erff(v0 * 0.7071067811865476f));
                    v1 = 0.5f * v1 * (1.f + erff(v1 * 0.7071067811865476f));
                    __nv_bfloat162 hh, ll;
                    split2(v0, hh.x, ll.x); split2(v1, hh.y, ll.y);
                    *(__nv_bfloat162*)(Oh + dbase + col) = hh;
                    *(__nv_bfloat162*)(Ol + dbase + col) = ll;
                } else {
                    float2 xr = *(const float2*)(resid + dbase + col);
                    *(float2*)(Co + dbase + col) = make_float2(v0 + xr.x, v1 + xr.y);
                }
            }
        }
    }
}

// ---------------- fused attention: broadcast k/v, register q/acc ----------
#define SSTR 51
__global__ __launch_bounds__(64) void attn_kernel(
    const float* __restrict__ qkv, const float* __restrict__ rpb,
    __nv_bfloat16* __restrict__ oh, __nv_bfloat16* __restrict__ ol) {
    int blk = blockIdx.x;
    int head = blk % NH;
    int b_ = blk / NH;
    int w = b_ & 63;
    int wh = w >> 3, ww = w & 7;

    __shared__ float ks[Nn * HD];
    __shared__ float vs[Nn * HD];
    __shared__ float ss[Nn * SSTR];
    __shared__ float biasv[169];
    __shared__ int grp[Nn];

    int t = threadIdx.x;
    for (int idx = t; idx < Nn * 8; idx += 64) {
        int row = idx >> 3, d4 = idx & 7;
        const float* base = qkv + ((size_t)(b_ * Nn + row)) * (3 * Cc) + head * HD + d4 * 4;
        *(float4*)(ks + row * HD + d4 * 4) = *(const float4*)(base + Cc);
        *(float4*)(vs + row * HD + d4 * 4) = *(const float4*)(base + 2 * Cc);
    }
    for (int i = t; i < 169; i += 64) biasv[i] = rpb[i * NH + head];
    if (t < Nn) {
        int hr = wh * WS + t / WS, wr = ww * WS + t % WS;
        int rh = hr < 49 ? 0 : (hr < 53 ? 1 : 2);
        int rw = wr < 49 ? 0 : (wr < 53 ? 1 : 2);
        grp[t] = rh * 3 + rw;
    }
    __syncthreads();

    const int i = t;
    const bool act = (i < Nn);
    int ri = 0, ci = 0, gi = 0;
    if (act) { ri = i / WS; ci = i - ri * WS; gi = grp[i]; }

    float4 qv[8];
    if (act) {
        const float4* qsrc = (const float4*)(qkv + ((size_t)(b_ * Nn + i)) * (3 * Cc) + head * HD);
        #pragma unroll
        for (int d4 = 0; d4 < 8; d4++) qv[d4] = qsrc[d4];
    }

    #pragma unroll 7
    for (int j = 0; j < Nn; j++) {
        const float4* kj = (const float4*)(ks + j * HD);
        float acc = 0.f;
        #pragma unroll
        for (int d4 = 0; d4 < 8; d4++) {
            float4 kk = kj[d4];
            acc += qv[d4].x * kk.x + qv[d4].y * kk.y + qv[d4].z * kk.z + qv[d4].w * kk.w;
        }
        if (act) {
            int rj = j / WS, cj = j - rj * WS;
            float bias = biasv[(ri - rj + 6) * 13 + (ci - cj + 6)];
            float msk = (gi != grp[j]) ? -100.f : 0.f;
            ss[i * SSTR + j] = acc * SCALE + bias + msk;
        }
    }

    float inv = 0.f;
    if (act) {
        float mx = -1e30f;
        #pragma unroll 7
        for (int j = 0; j < Nn; j++) mx = fmaxf(mx, ss[i * SSTR + j]);
        float sm = 0.f;
        #pragma unroll 7
        for (int j = 0; j < Nn; j++) {
            float e = __expf(ss[i * SSTR + j] - mx);
            ss[i * SSTR + j] = e;
            sm += e;
        }
        inv = 1.f / sm;
    }

    float4 acc[8];
    #pragma unroll
    for (int d4 = 0; d4 < 8; d4++) acc[d4] = make_float4(0.f, 0.f, 0.f, 0.f);
    #pragma unroll 7
    for (int j = 0; j < Nn; j++) {
        const float4* vj = (const float4*)(vs + j * HD);
        float p = act ? ss[i * SSTR + j] : 0.f;
        #pragma unroll
        for (int d4 = 0; d4 < 8; d4++) {
            float4 vv = vj[d4];
            acc[d4].x = fmaf(p, vv.x, acc[d4].x);
            acc[d4].y = fmaf(p, vv.y, acc[d4].y);
            acc[d4].z = fmaf(p, vv.z, acc[d4].z);
            acc[d4].w = fmaf(p, vv.w, acc[d4].w);
        }
    }

    if (act) {
        size_t base = ((size_t)(b_ * Nn + i)) * Cc + head * HD;
        #pragma unroll
        for (int d4 = 0; d4 < 8; d4++) {
            float4 o = acc[d4];
            o.x *= inv; o.y *= inv; o.z *= inv; o.w *= inv;
            __nv_bfloat162 h0, h1, l0, l1;
            split2(o.x, h0.x, l0.x); split2(o.y, h0.y, l0.y);
            split2(o.z, h1.x, l1.x); split2(o.w, h1.y, l1.y);
            *(__nv_bfloat162*)(oh + base + d4 * 4)     = h0;
            *(__nv_bfloat162*)(oh + base + d4 * 4 + 2) = h1;
            *(__nv_bfloat162*)(ol + base + d4 * 4)     = l0;
            *(__nv_bfloat162*)(ol + base + d4 * 4 + 2) = l1;
        }
    }
}

// ---------------- launch ----------------
extern "C" void kernel_launch(void* const* d_in, const int* in_sizes, int n_in,
                              void* d_out, int out_size) {
    const float* x       = (const float*)d_in[0];
    const float* norm1_g = (const float*)d_in[1];
    const float* norm1_b = (const float*)d_in[2];
    const float* qkv_w   = (const float*)d_in[3];
    const float* qkv_b   = (const float*)d_in[4];
    const float* proj_w  = (const float*)d_in[5];
    const float* proj_b  = (const float*)d_in[6];
    const float* rpb     = (const float*)d_in[7];
    const float* norm2_g = (const float*)d_in[8];
    const float* norm2_b = (const float*)d_in[9];
    const float* fc1_w   = (const float*)d_in[10];
    const float* fc1_b   = (const float*)d_in[11];
    const float* fc2_w   = (const float*)d_in[12];
    const float* fc2_b   = (const float*)d_in[13];
    float* out = (float*)d_out;

    __nv_bfloat16 *xwh, *xwl, *aoh, *aol, *hidh, *hidl;
    __nv_bfloat16 *wqh, *wql, *wph, *wpl, *f1h, *f1l, *f2h, *f2l;
    float *qkv, *h;
    cudaGetSymbolAddress((void**)&xwh, g_xw_h);   cudaGetSymbolAddress((void**)&xwl, g_xw_l);
    cudaGetSymbolAddress((void**)&qkv, g_qkv);
    cudaGetSymbolAddress((void**)&aoh, g_ao_h);   cudaGetSymbolAddress((void**)&aol, g_ao_l);
    cudaGetSymbolAddress((void**)&h,   g_h);
    cudaGetSymbolAddress((void**)&hidh, g_hid_h); cudaGetSymbolAddress((void**)&hidl, g_hid_l);
    cudaGetSymbolAddress((void**)&wqh, g_wq_h);   cudaGetSymbolAddress((void**)&wql, g_wq_l);
    cudaGetSymbolAddress((void**)&wph, g_wp_h);   cudaGetSymbolAddress((void**)&wpl, g_wp_l);
    cudaGetSymbolAddress((void**)&f1h, g_f1_h);   cudaGetSymbolAddress((void**)&f1l, g_f1_l);
    cudaGetSymbolAddress((void**)&f2h, g_f2_h);   cudaGetSymbolAddress((void**)&f2l, g_f2_l);

    cudaFuncSetAttribute(gemm_mma<3 * Cc, Cc, 0>, cudaFuncAttributeMaxDynamicSharedMemorySize, SMEM_TOT);
    cudaFuncSetAttribute(gemm_mma<Cc, Cc, 2>,     cudaFuncAttributeMaxDynamicSharedMemorySize, SMEM_TOT);
    cudaFuncSetAttribute(gemm_mma<HID, Cc, 1>,    cudaFuncAttributeMaxDynamicSharedMemorySize, SMEM_TOT);
    cudaFuncSetAttribute(gemm_mma<Cc, HID, 3>,    cudaFuncAttributeMaxDynamicSharedMemorySize, SMEM_TOT);

    convert_kernel<<<(3 * Cc * Cc + 255) / 256, 256>>>(qkv_w, wqh, wql, 3 * Cc * Cc);
    convert_kernel<<<(Cc * Cc + 255) / 256, 256>>>(proj_w, wph, wpl, Cc * Cc);
    convert_kernel<<<(HID * Cc + 255) / 256, 256>>>(fc1_w, f1h, f1l, HID * Cc);
    convert_kernel<<<(Cc * HID + 255) / 256, 256>>>(fc2_w, f2h, f2l, Cc * HID);

    ln1_gather_kernel<<<ROWS / 8, 256>>>(x, norm1_g, norm1_b, xwh, xwl);

    gemm_mma<3 * Cc, Cc, 0><<<dim3(9, ROWS / 256), 256, SMEM_TOT>>>(
        xwh, xwl, wqh, wql, qkv_b, qkv, nullptr, nullptr, nullptr);

    attn_kernel<<<BW * NH, 64>>>(qkv, rpb, aoh, aol);

    gemm_mma<Cc, Cc, 2><<<dim3(3, ROWS / 256), 256, SMEM_TOT>>>(
        aoh, aol, wph, wpl, proj_b, h, x, nullptr, nullptr);

    ln_plain_kernel<<<ROWS / 8, 256>>>(h, norm2_g, norm2_b, xwh, xwl);

    gemm_mma<HID, Cc, 1><<<dim3(12, ROWS / 256), 256, SMEM_TOT>>>(
        xwh, xwl, f1h, f1l, fc1_b, nullptr, nullptr, hidh, hidl);

    gemm_mma<Cc, HID, 3><<<dim3(3, ROWS / 256), 256, SMEM_TOT>>>(
        hidh, hidl, f2h, f2l, fc2_b, out, h, nullptr, nullptr);
}

// round 7
// speedup vs baseline: 1.3345x; 1.3345x over previous
#include <cuda_runtime.h>
#include <cuda_fp16.h>
#include <math.h>
#include <stdint.h>

// ---------------- problem constants ----------------
#define Bn    32
#define Hs    56
#define Ws_   56
#define Cc    192
#define WS    7
#define SS    3
#define NH    6
#define Nn    49
#define HD    32
#define BW    2048
#define ROWS  100352
#define HID   768
#define SCALE 0.17677669529663687f
#define LNEPS 1e-5f

// ---------------- helpers ----------------
__device__ __forceinline__ uint32_t smem_u32(const void* p) {
    uint32_t a;
    asm("{ .reg .u64 t; cvta.to.shared.u64 t, %1; cvt.u32.u64 %0, t; }" : "=r"(a) : "l"(p));
    return a;
}

#define LDSM4(r, a) \
    asm volatile("ldmatrix.sync.aligned.m8n8.x4.shared.b16 {%0,%1,%2,%3}, [%4];" \
        : "=r"((r)[0]), "=r"((r)[1]), "=r"((r)[2]), "=r"((r)[3]) : "r"(a))

#define MMA16816(d, a, b0, b1) \
    asm volatile("mma.sync.aligned.m16n8k16.row.col.f32.f16.f16.f32 " \
        "{%0,%1,%2,%3}, {%4,%5,%6,%7}, {%8,%9}, {%0,%1,%2,%3};" \
        : "+f"((d)[0]), "+f"((d)[1]), "+f"((d)[2]), "+f"((d)[3]) \
        : "r"((a)[0]), "r"((a)[1]), "r"((a)[2]), "r"((a)[3]), "r"(b0), "r"(b1))

__device__ __forceinline__ void split2h(float v, __half& h, __half& l) {
    h = __float2half(v);
    l = __float2half(v - __half2float(h));
}

// ---------------- scratch ----------------
__device__ __half g_xw_h[(size_t)ROWS * Cc];
__device__ __half g_xw_l[(size_t)ROWS * Cc];
__device__ float  g_qkv[(size_t)ROWS * 3 * Cc];
__device__ __half g_ao_h[(size_t)ROWS * Cc];
__device__ __half g_ao_l[(size_t)ROWS * Cc];
__device__ float  g_h[(size_t)ROWS * Cc];
__device__ __half g_hid_h[(size_t)ROWS * HID];
__device__ __half g_hid_l[(size_t)ROWS * HID];
__device__ __half g_wq[3 * Cc * Cc];
__device__ __half g_wp[Cc * Cc];
__device__ __half g_f1[HID * Cc];
__device__ __half g_f2[Cc * HID];

// ---------------- weight convert (single fp16) ----------------
__global__ void convert_kernel(const float* __restrict__ w,
                               __half* __restrict__ o, int n) {
    int i = blockIdx.x * 256 + threadIdx.x;
    if (i < n) o[i] = __float2half(w[i]);
}

// ---------------- LN kernels (write fp16 hi/lo) ----------------
__global__ void ln1_gather_kernel(const float* __restrict__ x,
                                  const float* __restrict__ g, const float* __restrict__ b,
                                  __half* __restrict__ oh, __half* __restrict__ ol) {
    int r = blockIdx.x * 8 + (threadIdx.x >> 5);
    if (r >= ROWS) return;
    int lane = threadIdx.x & 31;
    int b_ = r / Nn, t = r - b_ * Nn;
    int bb = b_ >> 6, w = b_ & 63;
    int hr = (w >> 3) * WS + t / WS;
    int wr = (w & 7) * WS + t % WS;
    int sh = hr + SS; if (sh >= Hs) sh -= Hs;
    int sw = wr + SS; if (sw >= Ws_) sw -= Ws_;
    const float* src = x + ((size_t)(bb * Hs * Ws_ + sh * Ws_ + sw)) * Cc;
    float v[6], s = 0.f, s2 = 0.f;
    #pragma unroll
    for (int j = 0; j < 6; j++) { v[j] = src[lane + 32 * j]; s += v[j]; s2 += v[j] * v[j]; }
    #pragma unroll
    for (int o = 16; o; o >>= 1) { s += __shfl_xor_sync(~0u, s, o); s2 += __shfl_xor_sync(~0u, s2, o); }
    float mu = s * (1.f / Cc), var = s2 * (1.f / Cc) - mu * mu;
    float rs = rsqrtf(var + LNEPS);
    size_t d0 = (size_t)r * Cc;
    #pragma unroll
    for (int j = 0; j < 6; j++) {
        int c = lane + 32 * j;
        float y = (v[j] - mu) * rs * g[c] + b[c];
        split2h(y, oh[d0 + c], ol[d0 + c]);
    }
}

__global__ void ln_plain_kernel(const float* __restrict__ x,
                                const float* __restrict__ g, const float* __restrict__ b,
                                __half* __restrict__ oh, __half* __restrict__ ol) {
    int r = blockIdx.x * 8 + (threadIdx.x >> 5);
    if (r >= ROWS) return;
    int lane = threadIdx.x & 31;
    const float* src = x + (size_t)r * Cc;
    float v[6], s = 0.f, s2 = 0.f;
    #pragma unroll
    for (int j = 0; j < 6; j++) { v[j] = src[lane + 32 * j]; s += v[j]; s2 += v[j] * v[j]; }
    #pragma unroll
    for (int o = 16; o; o >>= 1) { s += __shfl_xor_sync(~0u, s, o); s2 += __shfl_xor_sync(~0u, s2, o); }
    float mu = s * (1.f / Cc), var = s2 * (1.f / Cc) - mu * mu;
    float rs = rsqrtf(var + LNEPS);
    size_t d0 = (size_t)r * Cc;
    #pragma unroll
    for (int j = 0; j < 6; j++) {
        int c = lane + 32 * j;
        float y = (v[j] - mu) * rs * g[c] + b[c];
        split2h(y, oh[d0 + c], ol[d0 + c]);
    }
}

// ---------------- mma.sync fp16 GEMM, 2-term A split, fp16 weights ----------
// Block tile 128x64, BK=32, 8 warps: warp grid 4(m) x 2(n), warp tile 32x32.
#define BKt   32
#define ASTR  40                       // 32 + 8 pad (half elems)
#define OFF_AH 0
#define OFF_AL 10240
#define OFF_BH 20480
#define BUF_SZ 25600
#define SMEM_TOT (BUF_SZ * 2)          // 51200

template <int N_, int K_, int EPI>
__global__ __launch_bounds__(256) void gemm_mma(
    const __half* __restrict__ Ah, const __half* __restrict__ Al,
    const __half* __restrict__ Wh,
    const float* __restrict__ bias, float* __restrict__ Co,
    const float* __restrict__ resid,
    __half* __restrict__ Oh, __half* __restrict__ Ol) {
    extern __shared__ char smem[];
    const int t = threadIdx.x, lane = t & 31, wid = t >> 5;
    const int wm = wid & 3, wn = wid >> 2;
    const int m0 = blockIdx.y * 128, n0 = blockIdx.x * 64;
    constexpr int NKT = K_ / BKt;

    float acc[2][4][4];
    #pragma unroll
    for (int i = 0; i < 2; i++)
        #pragma unroll
        for (int j = 0; j < 4; j++)
            #pragma unroll
            for (int k = 0; k < 4; k++) acc[i][j][k] = 0.f;

    const int arow = t >> 2, akq = t & 3;
    {
        #pragma unroll
        for (int l = 0; l < 2; l++) {
            int row = arow + l * 64;
            uint32_t so = (uint32_t)row * (ASTR * 2) + akq * 16;
            *(uint4*)(smem + OFF_AH + so) = *(const uint4*)(Ah + (size_t)(m0 + row) * K_ + akq * 8);
            *(uint4*)(smem + OFF_AL + so) = *(const uint4*)(Al + (size_t)(m0 + row) * K_ + akq * 8);
        }
        uint32_t so = (uint32_t)arow * (ASTR * 2) + akq * 16;
        *(uint4*)(smem + OFF_BH + so) = *(const uint4*)(Wh + (size_t)(n0 + arow) * K_ + akq * 8);
    }
    __syncthreads();

    const int fr = lane & 15;
    const int fc = (lane >> 4) * 8;

    for (int kt = 0; kt < NKT; kt++) {
        char* buf = smem + (kt & 1) * BUF_SZ;
        uint4 pah[2], pal[2], pbh;
        if (kt + 1 < NKT) {
            int k0n = (kt + 1) * BKt;
            #pragma unroll
            for (int l = 0; l < 2; l++) {
                int row = arow + l * 64;
                pah[l] = *(const uint4*)(Ah + (size_t)(m0 + row) * K_ + k0n + akq * 8);
                pal[l] = *(const uint4*)(Al + (size_t)(m0 + row) * K_ + k0n + akq * 8);
            }
            pbh = *(const uint4*)(Wh + (size_t)(n0 + arow) * K_ + k0n + akq * 8);
        }

        const uint32_t sAh = smem_u32(buf + OFF_AH);
        const uint32_t sAl = smem_u32(buf + OFF_AL);
        const uint32_t sBh = smem_u32(buf + OFF_BH);

        #pragma unroll
        for (int ks = 0; ks < 2; ks++) {
            int col = ks * 16 + fc;
            uint32_t ah[2][4], al[2][4], bh[2][4];
            #pragma unroll
            for (int mf = 0; mf < 2; mf++) {
                uint32_t off = (uint32_t)(wm * 32 + mf * 16 + fr) * (ASTR * 2) + col * 2;
                LDSM4(ah[mf], sAh + off);
                LDSM4(al[mf], sAl + off);
            }
            #pragma unroll
            for (int nf2 = 0; nf2 < 2; nf2++) {
                uint32_t off = (uint32_t)(wn * 32 + nf2 * 16 + fr) * (ASTR * 2) + col * 2;
                LDSM4(bh[nf2], sBh + off);
            }
            #pragma unroll
            for (int mf = 0; mf < 2; mf++)
                #pragma unroll
                for (int nf = 0; nf < 4; nf++) {
                    int n2 = nf >> 1, sel = nf & 1;
                    MMA16816(acc[mf][nf], ah[mf], bh[n2][sel], bh[n2][sel + 2]);
                }
            #pragma unroll
            for (int mf = 0; mf < 2; mf++)
                #pragma unroll
                for (int nf = 0; nf < 4; nf++) {
                    int n2 = nf >> 1, sel = nf & 1;
                    MMA16816(acc[mf][nf], al[mf], bh[n2][sel], bh[n2][sel + 2]);
                }
        }

        if (kt + 1 < NKT) {
            char* nb = smem + ((kt + 1) & 1) * BUF_SZ;
            #pragma unroll
            for (int l = 0; l < 2; l++) {
                int row = arow + l * 64;
                uint32_t so = (uint32_t)row * (ASTR * 2) + akq * 16;
                *(uint4*)(nb + OFF_AH + so) = pah[l];
                *(uint4*)(nb + OFF_AL + so) = pal[l];
            }
            uint32_t so = (uint32_t)arow * (ASTR * 2) + akq * 16;
            *(uint4*)(nb + OFF_BH + so) = pbh;
            __syncthreads();
        }
    }

    const int r_in = lane >> 2, c_in = (lane & 3) * 2;
    #pragma unroll
    for (int mf = 0; mf < 2; mf++) {
        #pragma unroll
        for (int rr = 0; rr < 2; rr++) {
            int m = m0 + wm * 32 + mf * 16 + r_in + rr * 8;
            size_t dbase;
            if (EPI == 2) {
                int b_ = m / Nn, tok = m - b_ * Nn;
                int bb = b_ >> 6, w = b_ & 63;
                int hr = (w >> 3) * WS + tok / WS;
                int wr = (w & 7) * WS + tok % WS;
                int dh = hr + SS; if (dh >= Hs) dh -= Hs;
                int dw = wr + SS; if (dw >= Ws_) dw -= Ws_;
                dbase = ((size_t)(bb * Hs * Ws_ + dh * Ws_ + dw)) * Cc;
            } else {
                dbase = (size_t)m * N_;
            }
            #pragma unroll
            for (int nf = 0; nf < 4; nf++) {
                int col = n0 + wn * 32 + nf * 8 + c_in;
                float2 bv = *(const float2*)(bias + col);
                float v0 = acc[mf][nf][rr * 2]     + bv.x;
                float v1 = acc[mf][nf][rr * 2 + 1] + bv.y;
                if (EPI == 0) {
                    *(float2*)(Co + dbase + col) = make_float2(v0, v1);
                } else if (EPI == 1) {
                    v0 = 0.5f * v0 * (1.f + erff(v0 * 0.7071067811865476f));
                    v1 = 0.5f * v1 * (1.f + erff(v1 * 0.7071067811865476f));
                    __half2 hh, ll;
                    split2h(v0, hh.x, ll.x); split2h(v1, hh.y, ll.y);
                    *(__half2*)(Oh + dbase + col) = hh;
                    *(__half2*)(Ol + dbase + col) = ll;
                } else {
                    float2 xr = *(const float2*)(resid + dbase + col);
                    *(float2*)(Co + dbase + col) = make_float2(v0 + xr.x, v1 + xr.y);
                }
            }
        }
    }
}

// ---------------- fused attention: broadcast k/v, register q/acc ----------
#define SSTR 51
__global__ __launch_bounds__(64) void attn_kernel(
    const float* __restrict__ qkv, const float* __restrict__ rpb,
    __half* __restrict__ oh, __half* __restrict__ ol) {
    int blk = blockIdx.x;
    int head = blk % NH;
    int b_ = blk / NH;
    int w = b_ & 63;
    int wh = w >> 3, ww = w & 7;

    __shared__ float ks[Nn * HD];
    __shared__ float vs[Nn * HD];
    __shared__ float ss[Nn * SSTR];
    __shared__ float biasv[169];
    __shared__ int grp[Nn];

    int t = threadIdx.x;
    for (int idx = t; idx < Nn * 8; idx += 64) {
        int row = idx >> 3, d4 = idx & 7;
        const float* base = qkv + ((size_t)(b_ * Nn + row)) * (3 * Cc) + head * HD + d4 * 4;
        *(float4*)(ks + row * HD + d4 * 4) = *(const float4*)(base + Cc);
        *(float4*)(vs + row * HD + d4 * 4) = *(const float4*)(base + 2 * Cc);
    }
    for (int i = t; i < 169; i += 64) biasv[i] = rpb[i * NH + head];
    if (t < Nn) {
        int hr = wh * WS + t / WS, wr = ww * WS + t % WS;
        int rh = hr < 49 ? 0 : (hr < 53 ? 1 : 2);
        int rw = wr < 49 ? 0 : (wr < 53 ? 1 : 2);
        grp[t] = rh * 3 + rw;
    }
    __syncthreads();

    const int i = t;
    const bool act = (i < Nn);
    int ri = 0, ci = 0, gi = 0;
    if (act) { ri = i / WS; ci = i - ri * WS; gi = grp[i]; }

    float4 qv[8];
    if (act) {
        const float4* qsrc = (const float4*)(qkv + ((size_t)(b_ * Nn + i)) * (3 * Cc) + head * HD);
        #pragma unroll
        for (int d4 = 0; d4 < 8; d4++) qv[d4] = qsrc[d4];
    }

    #pragma unroll 7
    for (int j = 0; j < Nn; j++) {
        const float4* kj = (const float4*)(ks + j * HD);
        float acc = 0.f;
        #pragma unroll
        for (int d4 = 0; d4 < 8; d4++) {
            float4 kk = kj[d4];
            acc += qv[d4].x * kk.x + qv[d4].y * kk.y + qv[d4].z * kk.z + qv[d4].w * kk.w;
        }
        if (act) {
            int rj = j / WS, cj = j - rj * WS;
            float bias = biasv[(ri - rj + 6) * 13 + (ci - cj + 6)];
            float msk = (gi != grp[j]) ? -100.f : 0.f;
            ss[i * SSTR + j] = acc * SCALE + bias + msk;
        }
    }

    float inv = 0.f;
    if (act) {
        float mx = -1e30f;
        #pragma unroll 7
        for (int j = 0; j < Nn; j++) mx = fmaxf(mx, ss[i * SSTR + j]);
        float sm = 0.f;
        #pragma unroll 7
        for (int j = 0; j < Nn; j++) {
            float e = __expf(ss[i * SSTR + j] - mx);
            ss[i * SSTR + j] = e;
            sm += e;
        }
        inv = 1.f / sm;
    }

    float4 acc[8];
    #pragma unroll
    for (int d4 = 0; d4 < 8; d4++) acc[d4] = make_float4(0.f, 0.f, 0.f, 0.f);
    #pragma unroll 7
    for (int j = 0; j < Nn; j++) {
        const float4* vj = (const float4*)(vs + j * HD);
        float p = act ? ss[i * SSTR + j] : 0.f;
        #pragma unroll
        for (int d4 = 0; d4 < 8; d4++) {
            float4 vv = vj[d4];
            acc[d4].x = fmaf(p, vv.x, acc[d4].x);
            acc[d4].y = fmaf(p, vv.y, acc[d4].y);
            acc[d4].z = fmaf(p, vv.z, acc[d4].z);
            acc[d4].w = fmaf(p, vv.w, acc[d4].w);
        }
    }

    if (act) {
        size_t base = ((size_t)(b_ * Nn + i)) * Cc + head * HD;
        #pragma unroll
        for (int d4 = 0; d4 < 8; d4++) {
            float4 o = acc[d4];
            o.x *= inv; o.y *= inv; o.z *= inv; o.w *= inv;
            __half2 h0, h1, l0, l1;
            split2h(o.x, h0.x, l0.x); split2h(o.y, h0.y, l0.y);
            split2h(o.z, h1.x, l1.x); split2h(o.w, h1.y, l1.y);
            *(__half2*)(oh + base + d4 * 4)     = h0;
            *(__half2*)(oh + base + d4 * 4 + 2) = h1;
            *(__half2*)(ol + base + d4 * 4)     = l0;
            *(__half2*)(ol + base + d4 * 4 + 2) = l1;
        }
    }
}

// ---------------- launch ----------------
extern "C" void kernel_launch(void* const* d_in, const int* in_sizes, int n_in,
                              void* d_out, int out_size) {
    const float* x       = (const float*)d_in[0];
    const float* norm1_g = (const float*)d_in[1];
    const float* norm1_b = (const float*)d_in[2];
    const float* qkv_w   = (const float*)d_in[3];
    const float* qkv_b   = (const float*)d_in[4];
    const float* proj_w  = (const float*)d_in[5];
    const float* proj_b  = (const float*)d_in[6];
    const float* rpb     = (const float*)d_in[7];
    const float* norm2_g = (const float*)d_in[8];
    const float* norm2_b = (const float*)d_in[9];
    const float* fc1_w   = (const float*)d_in[10];
    const float* fc1_b   = (const float*)d_in[11];
    const float* fc2_w   = (const float*)d_in[12];
    const float* fc2_b   = (const float*)d_in[13];
    float* out = (float*)d_out;

    __half *xwh, *xwl, *aoh, *aol, *hidh, *hidl;
    __half *wq, *wp, *f1, *f2;
    float *qkv, *h;
    cudaGetSymbolAddress((void**)&xwh, g_xw_h);   cudaGetSymbolAddress((void**)&xwl, g_xw_l);
    cudaGetSymbolAddress((void**)&qkv, g_qkv);
    cudaGetSymbolAddress((void**)&aoh, g_ao_h);   cudaGetSymbolAddress((void**)&aol, g_ao_l);
    cudaGetSymbolAddress((void**)&h,   g_h);
    cudaGetSymbolAddress((void**)&hidh, g_hid_h); cudaGetSymbolAddress((void**)&hidl, g_hid_l);
    cudaGetSymbolAddress((void**)&wq, g_wq);
    cudaGetSymbolAddress((void**)&wp, g_wp);
    cudaGetSymbolAddress((void**)&f1, g_f1);
    cudaGetSymbolAddress((void**)&f2, g_f2);

    cudaFuncSetAttribute(gemm_mma<3 * Cc, Cc, 0>, cudaFuncAttributeMaxDynamicSharedMemorySize, SMEM_TOT);
    cudaFuncSetAttribute(gemm_mma<Cc, Cc, 2>,     cudaFuncAttributeMaxDynamicSharedMemorySize, SMEM_TOT);
    cudaFuncSetAttribute(gemm_mma<HID, Cc, 1>,    cudaFuncAttributeMaxDynamicSharedMemorySize, SMEM_TOT);
    cudaFuncSetAttribute(gemm_mma<Cc, HID, 3>,    cudaFuncAttributeMaxDynamicSharedMemorySize, SMEM_TOT);

    convert_kernel<<<(3 * Cc * Cc + 255) / 256, 256>>>(qkv_w, wq, 3 * Cc * Cc);
    convert_kernel<<<(Cc * Cc + 255) / 256, 256>>>(proj_w, wp, Cc * Cc);
    convert_kernel<<<(HID * Cc + 255) / 256, 256>>>(fc1_w, f1, HID * Cc);
    convert_kernel<<<(Cc * HID + 255) / 256, 256>>>(fc2_w, f2, Cc * HID);

    ln1_gather_kernel<<<ROWS / 8, 256>>>(x, norm1_g, norm1_b, xwh, xwl);

    gemm_mma<3 * Cc, Cc, 0><<<dim3(9, ROWS / 128), 256, SMEM_TOT>>>(
        xwh, xwl, wq, qkv_b, qkv, nullptr, nullptr, nullptr);

    attn_kernel<<<BW * NH, 64>>>(qkv, rpb, aoh, aol);

    gemm_mma<Cc, Cc, 2><<<dim3(3, ROWS / 128), 256, SMEM_TOT>>>(
        aoh, aol, wp, proj_b, h, x, nullptr, nullptr);

    ln_plain_kernel<<<ROWS / 8, 256>>>(h, norm2_g, norm2_b, xwh, xwl);

    gemm_mma<HID, Cc, 1><<<dim3(12, ROWS / 128), 256, SMEM_TOT>>>(
        xwh, xwl, f1, fc1_b, nullptr, nullptr, hidh, hidl);

    gemm_mma<Cc, HID, 3><<<dim3(3, ROWS / 128), 256, SMEM_TOT>>>(
        hidh, hidl, f2, fc2_b, out, h, nullptr, nullptr);
}

// round 8
// speedup vs baseline: 1.8724x; 1.4030x over previous
#include <cuda_runtime.h>
#include <cuda_fp16.h>
#include <math.h>
#include <stdint.h>

// ---------------- problem constants ----------------
#define Bn    32
#define Hs    56
#define Ws_   56
#define Cc    192
#define WS    7
#define SS    3
#define NH    6
#define Nn    49
#define HD    32
#define BW    2048
#define ROWS  100352
#define HID   768
#define SCALE 0.17677669529663687f
#define LNEPS 1e-5f

// ---------------- helpers ----------------
__device__ __forceinline__ uint32_t smem_u32(const void* p) {
    uint32_t a;
    asm("{ .reg .u64 t; cvta.to.shared.u64 t, %1; cvt.u32.u64 %0, t; }" : "=r"(a) : "l"(p));
    return a;
}

#define LDSM4(r, a) \
    asm volatile("ldmatrix.sync.aligned.m8n8.x4.shared.b16 {%0,%1,%2,%3}, [%4];" \
        : "=r"((r)[0]), "=r"((r)[1]), "=r"((r)[2]), "=r"((r)[3]) : "r"(a))

#define MMA16816(d, a, b0, b1) \
    asm volatile("mma.sync.aligned.m16n8k16.row.col.f32.f16.f16.f32 " \
        "{%0,%1,%2,%3}, {%4,%5,%6,%7}, {%8,%9}, {%0,%1,%2,%3};" \
        : "+f"((d)[0]), "+f"((d)[1]), "+f"((d)[2]), "+f"((d)[3]) \
        : "r"((a)[0]), "r"((a)[1]), "r"((a)[2]), "r"((a)[3]), "r"(b0), "r"(b1))

// ---------------- scratch ----------------
__device__ __half g_xw[(size_t)ROWS * Cc];
__device__ float  g_qkv[(size_t)ROWS * 3 * Cc];
__device__ __half g_ao[(size_t)ROWS * Cc];
__device__ float  g_h[(size_t)ROWS * Cc];
__device__ __half g_hid[(size_t)ROWS * HID];
__device__ __half g_wq[3 * Cc * Cc];
__device__ __half g_wp[Cc * Cc];
__device__ __half g_f1[HID * Cc];
__device__ __half g_f2[Cc * HID];

// ---------------- weight convert (single fp16) ----------------
__global__ void convert_kernel(const float* __restrict__ w,
                               __half* __restrict__ o, int n) {
    int i = blockIdx.x * 256 + threadIdx.x;
    if (i < n) o[i] = __float2half(w[i]);
}

// ---------------- LN kernels (write fp16) ----------------
__global__ void ln1_gather_kernel(const float* __restrict__ x,
                                  const float* __restrict__ g, const float* __restrict__ b,
                                  __half* __restrict__ o) {
    int r = blockIdx.x * 8 + (threadIdx.x >> 5);
    if (r >= ROWS) return;
    int lane = threadIdx.x & 31;
    int b_ = r / Nn, t = r - b_ * Nn;
    int bb = b_ >> 6, w = b_ & 63;
    int hr = (w >> 3) * WS + t / WS;
    int wr = (w & 7) * WS + t % WS;
    int sh = hr + SS; if (sh >= Hs) sh -= Hs;
    int sw = wr + SS; if (sw >= Ws_) sw -= Ws_;
    const float* src = x + ((size_t)(bb * Hs * Ws_ + sh * Ws_ + sw)) * Cc;
    float v[6], s = 0.f, s2 = 0.f;
    #pragma unroll
    for (int j = 0; j < 6; j++) { v[j] = src[lane + 32 * j]; s += v[j]; s2 += v[j] * v[j]; }
    #pragma unroll
    for (int o2 = 16; o2; o2 >>= 1) { s += __shfl_xor_sync(~0u, s, o2); s2 += __shfl_xor_sync(~0u, s2, o2); }
    float mu = s * (1.f / Cc), var = s2 * (1.f / Cc) - mu * mu;
    float rs = rsqrtf(var + LNEPS);
    size_t d0 = (size_t)r * Cc;
    #pragma unroll
    for (int j = 0; j < 6; j++) {
        int c = lane + 32 * j;
        o[d0 + c] = __float2half((v[j] - mu) * rs * g[c] + b[c]);
    }
}

__global__ void ln_plain_kernel(const float* __restrict__ x,
                                const float* __restrict__ g, const float* __restrict__ b,
                                __half* __restrict__ o) {
    int r = blockIdx.x * 8 + (threadIdx.x >> 5);
    if (r >= ROWS) return;
    int lane = threadIdx.x & 31;
    const float* src = x + (size_t)r * Cc;
    float v[6], s = 0.f, s2 = 0.f;
    #pragma unroll
    for (int j = 0; j < 6; j++) { v[j] = src[lane + 32 * j]; s += v[j]; s2 += v[j] * v[j]; }
    #pragma unroll
    for (int o2 = 16; o2; o2 >>= 1) { s += __shfl_xor_sync(~0u, s, o2); s2 += __shfl_xor_sync(~0u, s2, o2); }
    float mu = s * (1.f / Cc), var = s2 * (1.f / Cc) - mu * mu;
    float rs = rsqrtf(var + LNEPS);
    size_t d0 = (size_t)r * Cc;
    #pragma unroll
    for (int j = 0; j < 6; j++) {
        int c = lane + 32 * j;
        o[d0 + c] = __float2half((v[j] - mu) * rs * g[c] + b[c]);
    }
}

// ---------------- mma.sync fp16 GEMM (single precision term) ----------
// Block tile 128x64, BK=32, 8 warps: warp grid 4(m) x 2(n), warp tile 32x32.
#define BKt   32
#define ASTR  40                       // 32 + 8 pad (half elems)
#define OFF_A  0
#define OFF_B  10240
#define BUF_SZ 15360
#define SMEM_TOT (BUF_SZ * 2)          // 30720

template <int N_, int K_, int EPI>
__global__ __launch_bounds__(256) void gemm_mma(
    const __half* __restrict__ A, const __half* __restrict__ Wh,
    const float* __restrict__ bias, float* __restrict__ Co,
    const float* __restrict__ resid, __half* __restrict__ Oh) {
    extern __shared__ char smem[];
    const int t = threadIdx.x, lane = t & 31, wid = t >> 5;
    const int wm = wid & 3, wn = wid >> 2;
    const int m0 = blockIdx.y * 128, n0 = blockIdx.x * 64;
    constexpr int NKT = K_ / BKt;

    float acc[2][4][4];
    #pragma unroll
    for (int i = 0; i < 2; i++)
        #pragma unroll
        for (int j = 0; j < 4; j++)
            #pragma unroll
            for (int k = 0; k < 4; k++) acc[i][j][k] = 0.f;

    const int arow = t >> 2, akq = t & 3;
    {
        #pragma unroll
        for (int l = 0; l < 2; l++) {
            int row = arow + l * 64;
            uint32_t so = (uint32_t)row * (ASTR * 2) + akq * 16;
            *(uint4*)(smem + OFF_A + so) = *(const uint4*)(A + (size_t)(m0 + row) * K_ + akq * 8);
        }
        uint32_t so = (uint32_t)arow * (ASTR * 2) + akq * 16;
        *(uint4*)(smem + OFF_B + so) = *(const uint4*)(Wh + (size_t)(n0 + arow) * K_ + akq * 8);
    }
    __syncthreads();

    const int fr = lane & 15;
    const int fc = (lane >> 4) * 8;

    for (int kt = 0; kt < NKT; kt++) {
        char* buf = smem + (kt & 1) * BUF_SZ;
        uint4 pa[2], pb;
        if (kt + 1 < NKT) {
            int k0n = (kt + 1) * BKt;
            #pragma unroll
            for (int l = 0; l < 2; l++) {
                int row = arow + l * 64;
                pa[l] = *(const uint4*)(A + (size_t)(m0 + row) * K_ + k0n + akq * 8);
            }
            pb = *(const uint4*)(Wh + (size_t)(n0 + arow) * K_ + k0n + akq * 8);
        }

        const uint32_t sA = smem_u32(buf + OFF_A);
        const uint32_t sB = smem_u32(buf + OFF_B);

        #pragma unroll
        for (int ks = 0; ks < 2; ks++) {
            int col = ks * 16 + fc;
            uint32_t ah[2][4], bh[2][4];
            #pragma unroll
            for (int mf = 0; mf < 2; mf++) {
                uint32_t off = (uint32_t)(wm * 32 + mf * 16 + fr) * (ASTR * 2) + col * 2;
                LDSM4(ah[mf], sA + off);
            }
            #pragma unroll
            for (int nf2 = 0; nf2 < 2; nf2++) {
                uint32_t off = (uint32_t)(wn * 32 + nf2 * 16 + fr) * (ASTR * 2) + col * 2;
                LDSM4(bh[nf2], sB + off);
            }
            #pragma unroll
            for (int mf = 0; mf < 2; mf++)
                #pragma unroll
                for (int nf = 0; nf < 4; nf++) {
                    int n2 = nf >> 1, sel = nf & 1;
                    MMA16816(acc[mf][nf], ah[mf], bh[n2][sel], bh[n2][sel + 2]);
                }
        }

        if (kt + 1 < NKT) {
            char* nb = smem + ((kt + 1) & 1) * BUF_SZ;
            #pragma unroll
            for (int l = 0; l < 2; l++) {
                int row = arow + l * 64;
                uint32_t so = (uint32_t)row * (ASTR * 2) + akq * 16;
                *(uint4*)(nb + OFF_A + so) = pa[l];
            }
            uint32_t so = (uint32_t)arow * (ASTR * 2) + akq * 16;
            *(uint4*)(nb + OFF_B + so) = pb;
            __syncthreads();
        }
    }

    const int r_in = lane >> 2, c_in = (lane & 3) * 2;
    #pragma unroll
    for (int mf = 0; mf < 2; mf++) {
        #pragma unroll
        for (int rr = 0; rr < 2; rr++) {
            int m = m0 + wm * 32 + mf * 16 + r_in + rr * 8;
            size_t dbase;
            if (EPI == 2) {
                int b_ = m / Nn, tok = m - b_ * Nn;
                int bb = b_ >> 6, w = b_ & 63;
                int hr = (w >> 3) * WS + tok / WS;
                int wr = (w & 7) * WS + tok % WS;
                int dh = hr + SS; if (dh >= Hs) dh -= Hs;
                int dw = wr + SS; if (dw >= Ws_) dw -= Ws_;
                dbase = ((size_t)(bb * Hs * Ws_ + dh * Ws_ + dw)) * Cc;
            } else {
                dbase = (size_t)m * N_;
            }
            #pragma unroll
            for (int nf = 0; nf < 4; nf++) {
                int col = n0 + wn * 32 + nf * 8 + c_in;
                float2 bv = *(const float2*)(bias + col);
                float v0 = acc[mf][nf][rr * 2]     + bv.x;
                float v1 = acc[mf][nf][rr * 2 + 1] + bv.y;
                if (EPI == 0) {
                    *(float2*)(Co + dbase + col) = make_float2(v0, v1);
                } else if (EPI == 1) {
                    v0 = 0.5f * v0 * (1.f + erff(v0 * 0.7071067811865476f));
                    v1 = 0.5f * v1 * (1.f + erff(v1 * 0.7071067811865476f));
                    __half2 hh;
                    hh.x = __float2half(v0); hh.y = __float2half(v1);
                    *(__half2*)(Oh + dbase + col) = hh;
                } else {
                    float2 xr = *(const float2*)(resid + dbase + col);
                    *(float2*)(Co + dbase + col) = make_float2(v0 + xr.x, v1 + xr.y);
                }
            }
        }
    }
}

// ---------------- fused attention: broadcast k/v, register q/acc ----------
#define SSTR 51
__global__ __launch_bounds__(64) void attn_kernel(
    const float* __restrict__ qkv, const float* __restrict__ rpb,
    __half* __restrict__ oh) {
    int blk = blockIdx.x;
    int head = blk % NH;
    int b_ = blk / NH;
    int w = b_ & 63;
    int wh = w >> 3, ww = w & 7;

    __shared__ float ks[Nn * HD];
    __shared__ float vs[Nn * HD];
    __shared__ float ss[Nn * SSTR];
    __shared__ float biasv[169];
    __shared__ int grp[Nn];

    int t = threadIdx.x;
    for (int idx = t; idx < Nn * 8; idx += 64) {
        int row = idx >> 3, d4 = idx & 7;
        const float* base = qkv + ((size_t)(b_ * Nn + row)) * (3 * Cc) + head * HD + d4 * 4;
        *(float4*)(ks + row * HD + d4 * 4) = *(const float4*)(base + Cc);
        *(float4*)(vs + row * HD + d4 * 4) = *(const float4*)(base + 2 * Cc);
    }
    for (int i = t; i < 169; i += 64) biasv[i] = rpb[i * NH + head];
    if (t < Nn) {
        int hr = wh * WS + t / WS, wr = ww * WS + t % WS;
        int rh = hr < 49 ? 0 : (hr < 53 ? 1 : 2);
        int rw = wr < 49 ? 0 : (wr < 53 ? 1 : 2);
        grp[t] = rh * 3 + rw;
    }
    __syncthreads();

    const int i = t;
    const bool act = (i < Nn);
    int ri = 0, ci = 0, gi = 0;
    if (act) { ri = i / WS; ci = i - ri * WS; gi = grp[i]; }

    float4 qv[8];
    if (act) {
        const float4* qsrc = (const float4*)(qkv + ((size_t)(b_ * Nn + i)) * (3 * Cc) + head * HD);
        #pragma unroll
        for (int d4 = 0; d4 < 8; d4++) qv[d4] = qsrc[d4];
    }

    #pragma unroll 7
    for (int j = 0; j < Nn; j++) {
        const float4* kj = (const float4*)(ks + j * HD);
        float acc = 0.f;
        #pragma unroll
        for (int d4 = 0; d4 < 8; d4++) {
            float4 kk = kj[d4];
            acc += qv[d4].x * kk.x + qv[d4].y * kk.y + qv[d4].z * kk.z + qv[d4].w * kk.w;
        }
        if (act) {
            int rj = j / WS, cj = j - rj * WS;
            float bias = biasv[(ri - rj + 6) * 13 + (ci - cj + 6)];
            float msk = (gi != grp[j]) ? -100.f : 0.f;
            ss[i * SSTR + j] = acc * SCALE + bias + msk;
        }
    }

    float inv = 0.f;
    if (act) {
        float mx = -1e30f;
        #pragma unroll 7
        for (int j = 0; j < Nn; j++) mx = fmaxf(mx, ss[i * SSTR + j]);
        float sm = 0.f;
        #pragma unroll 7
        for (int j = 0; j < Nn; j++) {
            float e = __expf(ss[i * SSTR + j] - mx);
            ss[i * SSTR + j] = e;
            sm += e;
        }
        inv = 1.f / sm;
    }

    float4 acc[8];
    #pragma unroll
    for (int d4 = 0; d4 < 8; d4++) acc[d4] = make_float4(0.f, 0.f, 0.f, 0.f);
    #pragma unroll 7
    for (int j = 0; j < Nn; j++) {
        const float4* vj = (const float4*)(vs + j * HD);
        float p = act ? ss[i * SSTR + j] : 0.f;
        #pragma unroll
        for (int d4 = 0; d4 < 8; d4++) {
            float4 vv = vj[d4];
            acc[d4].x = fmaf(p, vv.x, acc[d4].x);
            acc[d4].y = fmaf(p, vv.y, acc[d4].y);
            acc[d4].z = fmaf(p, vv.z, acc[d4].z);
            acc[d4].w = fmaf(p, vv.w, acc[d4].w);
        }
    }

    if (act) {
        size_t base = ((size_t)(b_ * Nn + i)) * Cc + head * HD;
        #pragma unroll
        for (int d4 = 0; d4 < 8; d4++) {
            float4 o = acc[d4];
            __half2 h0, h1;
            h0.x = __float2half(o.x * inv); h0.y = __float2half(o.y * inv);
            h1.x = __float2half(o.z * inv); h1.y = __float2half(o.w * inv);
            *(__half2*)(oh + base + d4 * 4)     = h0;
            *(__half2*)(oh + base + d4 * 4 + 2) = h1;
        }
    }
}

// ---------------- launch ----------------
extern "C" void kernel_launch(void* const* d_in, const int* in_sizes, int n_in,
                              void* d_out, int out_size) {
    const float* x       = (const float*)d_in[0];
    const float* norm1_g = (const float*)d_in[1];
    const float* norm1_b = (const float*)d_in[2];
    const float* qkv_w   = (const float*)d_in[3];
    const float* qkv_b   = (const float*)d_in[4];
    const float* proj_w  = (const float*)d_in[5];
    const float* proj_b  = (const float*)d_in[6];
    const float* rpb     = (const float*)d_in[7];
    const float* norm2_g = (const float*)d_in[8];
    const float* norm2_b = (const float*)d_in[9];
    const float* fc1_w   = (const float*)d_in[10];
    const float* fc1_b   = (const float*)d_in[11];
    const float* fc2_w   = (const float*)d_in[12];
    const float* fc2_b   = (const float*)d_in[13];
    float* out = (float*)d_out;

    __half *xw, *ao, *hid, *wq, *wp, *f1, *f2;
    float *qkv, *h;
    cudaGetSymbolAddress((void**)&xw, g_xw);
    cudaGetSymbolAddress((void**)&qkv, g_qkv);
    cudaGetSymbolAddress((void**)&ao, g_ao);
    cudaGetSymbolAddress((void**)&h,  g_h);
    cudaGetSymbolAddress((void**)&hid, g_hid);
    cudaGetSymbolAddress((void**)&wq, g_wq);
    cudaGetSymbolAddress((void**)&wp, g_wp);
    cudaGetSymbolAddress((void**)&f1, g_f1);
    cudaGetSymbolAddress((void**)&f2, g_f2);

    cudaFuncSetAttribute(gemm_mma<3 * Cc, Cc, 0>, cudaFuncAttributeMaxDynamicSharedMemorySize, SMEM_TOT);
    cudaFuncSetAttribute(gemm_mma<Cc, Cc, 2>,     cudaFuncAttributeMaxDynamicSharedMemorySize, SMEM_TOT);
    cudaFuncSetAttribute(gemm_mma<HID, Cc, 1>,    cudaFuncAttributeMaxDynamicSharedMemorySize, SMEM_TOT);
    cudaFuncSetAttribute(gemm_mma<Cc, HID, 3>,    cudaFuncAttributeMaxDynamicSharedMemorySize, SMEM_TOT);

    convert_kernel<<<(3 * Cc * Cc + 255) / 256, 256>>>(qkv_w, wq, 3 * Cc * Cc);
    convert_kernel<<<(Cc * Cc + 255) / 256, 256>>>(proj_w, wp, Cc * Cc);
    convert_kernel<<<(HID * Cc + 255) / 256, 256>>>(fc1_w, f1, HID * Cc);
    convert_kernel<<<(Cc * HID + 255) / 256, 256>>>(fc2_w, f2, Cc * HID);

    ln1_gather_kernel<<<ROWS / 8, 256>>>(x, norm1_g, norm1_b, xw);

    gemm_mma<3 * Cc, Cc, 0><<<dim3(9, ROWS / 128), 256, SMEM_TOT>>>(
        xw, wq, qkv_b, qkv, nullptr, nullptr);

    attn_kernel<<<BW * NH, 64>>>(qkv, rpb, ao);

    gemm_mma<Cc, Cc, 2><<<dim3(3, ROWS / 128), 256, SMEM_TOT>>>(
        ao, wp, proj_b, h, x, nullptr);

    ln_plain_kernel<<<ROWS / 8, 256>>>(h, norm2_g, norm2_b, xw);

    gemm_mma<HID, Cc, 1><<<dim3(12, ROWS / 128), 256, SMEM_TOT>>>(
        xw, f1, fc1_b, nullptr, nullptr, hid);

    gemm_mma<Cc, HID, 3><<<dim3(3, ROWS / 128), 256, SMEM_TOT>>>(
        hid, f2, fc2_b, out, h, nullptr);
}